// round 1
// baseline (speedup 1.0000x reference)
#include <cuda_runtime.h>
#include <cmath>

#define TOKENS 8192
#define SEQ 2048
#define DM 512
#define DFF 2048
#define NLAYER 12
#define NVOCAB 400

// ---------------- scratch (device globals: allocation-guard safe) ----------------
__device__ float g_h[TOKENS * DM];          // 16 MB
__device__ float g_qkv[TOKENS * 3 * DM];    // 50 MB
__device__ float g_attn[TOKENS * DM];       // 16 MB
__device__ float g_ff[TOKENS * DFF];        // 64 MB

// ---------------- embedding + sinusoidal PE ----------------
__global__ void embed_kernel(const int* __restrict__ x, const float* __restrict__ emb,
                             float* __restrict__ h)
{
    int t = blockIdx.x;            // token index 0..8191
    int s = t & (SEQ - 1);         // position within sequence
    int tok = x[t];
    const float C1 = -9.210340371976184f / 512.0f;  // -ln(10000)/d_model
    for (int d = threadIdx.x; d < DM; d += blockDim.x) {
        int p = d >> 1;
        float div = expf((float)(2 * p) * C1);
        float ang = (float)s * div;
        float pe = (d & 1) ? cosf(ang) : sinf(ang);
        h[(size_t)t * DM + d] = emb[(size_t)tok * DM + d] * 22.62741699796952f + pe;
    }
}

// ---------------- LayerNorm (row of 512, in-place safe) ----------------
__global__ void __launch_bounds__(128) ln_kernel(const float* __restrict__ in,
                                                 const float* __restrict__ g,
                                                 const float* __restrict__ b,
                                                 float* __restrict__ out)
{
    __shared__ float sh[8];
    int row = blockIdx.x;
    int t = threadIdx.x;
    float4 x = ((const float4*)(in + (size_t)row * DM))[t];

    float s = x.x + x.y + x.z + x.w;
    #pragma unroll
    for (int o = 16; o > 0; o >>= 1) s += __shfl_xor_sync(0xffffffffu, s, o);
    if ((t & 31) == 0) sh[t >> 5] = s;
    __syncthreads();
    float mean = (sh[0] + sh[1] + sh[2] + sh[3]) * (1.0f / DM);

    float dx = x.x - mean, dy = x.y - mean, dz = x.z - mean, dw = x.w - mean;
    float sq = dx * dx + dy * dy + dz * dz + dw * dw;
    #pragma unroll
    for (int o = 16; o > 0; o >>= 1) sq += __shfl_xor_sync(0xffffffffu, sq, o);
    if ((t & 31) == 0) sh[4 + (t >> 5)] = sq;
    __syncthreads();
    float var = (sh[4] + sh[5] + sh[6] + sh[7]) * (1.0f / DM);
    float rs = rsqrtf(var + 1e-5f);

    float4 gg = ((const float4*)g)[t];
    float4 bb = ((const float4*)b)[t];
    float4 o4;
    o4.x = dx * rs * gg.x + bb.x;
    o4.y = dy * rs * gg.y + bb.y;
    o4.z = dz * rs * gg.z + bb.z;
    o4.w = dw * rs * gg.w + bb.w;
    ((float4*)(out + (size_t)row * DM))[t] = o4;
}

// ---------------- causal linear attention (FAVOR elu+1), sequential scan ----------------
// One block per (batch, head). 64 threads; thread e owns state column S[:,e] in regs.
// Chunked: 32 timesteps staged in smem -> barrier-free inner scan.
__global__ void __launch_bounds__(64) attn_kernel(const float* __restrict__ qkv,
                                                  float* __restrict__ out)
{
    int b = blockIdx.x >> 3;
    int hh = blockIdx.x & 7;
    int e = threadIdx.x;

    __shared__ float ks[32][64];
    __shared__ float qs[32][64];
    __shared__ float vs[32][64];
    __shared__ float ps[32][65];   // padded: conflict-free row reduce
    __shared__ float dens[32];

    float S[64];
    #pragma unroll
    for (int d = 0; d < 64; d++) S[d] = 0.0f;
    float zc = 0.0f;  // running z_e (this thread's feature index)

    const float* base = qkv + (size_t)b * SEQ * (3 * DM) + hh * 64;
    float* ob = out + (size_t)b * SEQ * DM + hh * 64;

    for (int c0 = 0; c0 < SEQ; c0 += 32) {
        // stage chunk (coalesced, phi applied to q,k)
        #pragma unroll 4
        for (int j = 0; j < 32; j++) {
            const float* r = base + (size_t)(c0 + j) * (3 * DM);
            float qv = r[e], kv = r[DM + e], vv = r[2 * DM + e];
            qs[j][e] = (qv > 0.0f) ? qv + 1.0f : expf(qv);  // elu(x)+1
            ks[j][e] = (kv > 0.0f) ? kv + 1.0f : expf(kv);
            vs[j][e] = vv;
        }
        __syncthreads();

        // denominator prefix: z_e running sum, partials p[j][e] = q_j[e] * z_e(j)
        float z = zc;
        #pragma unroll
        for (int j = 0; j < 32; j++) { z += ks[j][e]; ps[j][e] = qs[j][e] * z; }
        zc = z;
        __syncthreads();

        if (e < 32) {
            float sum = 0.0f;
            #pragma unroll 8
            for (int d = 0; d < 64; d++) sum += ps[e][d];
            dens[e] = sum + 1e-6f;
        }
        __syncthreads();

        // main scan: update state column + numerator dot, no barriers
        for (int j = 0; j < 32; j++) {
            float ve = vs[j][e];
            float n0 = 0.f, n1 = 0.f, n2 = 0.f, n3 = 0.f;
            #pragma unroll
            for (int d = 0; d < 64; d += 4) {
                S[d + 0] = fmaf(ks[j][d + 0], ve, S[d + 0]); n0 = fmaf(qs[j][d + 0], S[d + 0], n0);
                S[d + 1] = fmaf(ks[j][d + 1], ve, S[d + 1]); n1 = fmaf(qs[j][d + 1], S[d + 1], n1);
                S[d + 2] = fmaf(ks[j][d + 2], ve, S[d + 2]); n2 = fmaf(qs[j][d + 2], S[d + 2], n2);
                S[d + 3] = fmaf(ks[j][d + 3], ve, S[d + 3]); n3 = fmaf(qs[j][d + 3], S[d + 3], n3);
            }
            ob[(size_t)(c0 + j) * DM + e] = ((n0 + n1) + (n2 + n3)) / dens[j];
        }
        __syncthreads();
    }
}

// ---------------- fp32 tiled GEMM: C = A[M,K] @ B[K,N] + bias (+res) (relu?) ----------------
// 128x128 block tile, BK=16, 256 threads, 8x8 register tile per thread.
template <bool RELU, bool RES>
__global__ void __launch_bounds__(256) sgemm_kernel(
    const float* __restrict__ A, const float* __restrict__ B,
    const float* __restrict__ bias, const float* __restrict__ Res,
    float* __restrict__ C, int M, int N, int K, int ldb, int ldc)
{
    __shared__ float As[16][128];
    __shared__ float Bs[16][128];

    int tid = threadIdx.x;
    int m0 = blockIdx.y * 128;
    int n0 = blockIdx.x * 128;
    bool fullN = (n0 + 128 <= N);

    float acc[8][8];
    #pragma unroll
    for (int i = 0; i < 8; i++)
        #pragma unroll
        for (int j = 0; j < 8; j++) acc[i][j] = 0.0f;

    int a_r = tid >> 2, a_c = (tid & 3) << 2;
    int b_r = tid >> 5, b_c = (tid & 31) << 2;
    int mm = (tid >> 4) << 3;
    int nn = (tid & 15) << 3;

    for (int kt = 0; kt < K; kt += 16) {
        // A tile (transposed into smem)
        #pragma unroll
        for (int p = 0; p < 2; p++) {
            int r = a_r + p * 64;
            float4 f = *(const float4*)(A + (size_t)(m0 + r) * K + kt + a_c);
            As[a_c + 0][r] = f.x; As[a_c + 1][r] = f.y;
            As[a_c + 2][r] = f.z; As[a_c + 3][r] = f.w;
        }
        // B tile
        #pragma unroll
        for (int p = 0; p < 2; p++) {
            int r = b_r + p * 8;
            const float* src = B + (size_t)(kt + r) * ldb + n0 + b_c;
            float4 f;
            if (fullN) {
                f = *(const float4*)src;
            } else {
                f.x = (n0 + b_c + 0 < N) ? src[0] : 0.0f;
                f.y = (n0 + b_c + 1 < N) ? src[1] : 0.0f;
                f.z = (n0 + b_c + 2 < N) ? src[2] : 0.0f;
                f.w = (n0 + b_c + 3 < N) ? src[3] : 0.0f;
            }
            *(float4*)(&Bs[r][b_c]) = f;
        }
        __syncthreads();

        #pragma unroll
        for (int k = 0; k < 16; k++) {
            float a[8], bb[8];
            *(float4*)(a)     = *(const float4*)(&As[k][mm]);
            *(float4*)(a + 4) = *(const float4*)(&As[k][mm + 4]);
            *(float4*)(bb)     = *(const float4*)(&Bs[k][nn]);
            *(float4*)(bb + 4) = *(const float4*)(&Bs[k][nn + 4]);
            #pragma unroll
            for (int i = 0; i < 8; i++)
                #pragma unroll
                for (int j = 0; j < 8; j++)
                    acc[i][j] = fmaf(a[i], bb[j], acc[i][j]);
        }
        __syncthreads();
    }

    #pragma unroll
    for (int i = 0; i < 8; i++) {
        int m = m0 + mm + i;
        #pragma unroll
        for (int j = 0; j < 8; j++) {
            int n = n0 + nn + j;
            if (n < N) {
                float v = acc[i][j] + bias[n];
                if (RES) v += Res[(size_t)m * ldc + n];
                if (RELU) v = fmaxf(v, 0.0f);
                C[(size_t)m * ldc + n] = v;
            }
        }
    }
}

// ---------------- launch ----------------
extern "C" void kernel_launch(void* const* d_in, const int* in_sizes, int n_in,
                              void* d_out, int out_size)
{
    const int*   x    = (const int*)d_in[0];
    const float* emb  = (const float*)d_in[1];
    const float* Wqkv = (const float*)d_in[2];
    const float* bqkv = (const float*)d_in[3];
    const float* Wo   = (const float*)d_in[4];
    const float* bo   = (const float*)d_in[5];
    const float* ln1g = (const float*)d_in[6];
    const float* ln1b = (const float*)d_in[7];
    const float* W1   = (const float*)d_in[8];
    const float* b1   = (const float*)d_in[9];
    const float* W2   = (const float*)d_in[10];
    const float* b2   = (const float*)d_in[11];
    const float* ln2g = (const float*)d_in[12];
    const float* ln2b = (const float*)d_in[13];
    const float* lnfg = (const float*)d_in[14];
    const float* lnfb = (const float*)d_in[15];
    const float* Wout = (const float*)d_in[16];
    const float* bout = (const float*)d_in[17];
    float* out = (float*)d_out;

    float *h, *qkv, *attn, *ff;
    cudaGetSymbolAddress((void**)&h,    g_h);
    cudaGetSymbolAddress((void**)&qkv,  g_qkv);
    cudaGetSymbolAddress((void**)&attn, g_attn);
    cudaGetSymbolAddress((void**)&ff,   g_ff);

    embed_kernel<<<TOKENS, 128>>>(x, emb, h);

    dim3 gN512(4, TOKENS / 128);
    dim3 gN2048(16, TOKENS / 128);
    dim3 gNout((NVOCAB + 127) / 128, TOKENS / 128);

    for (int l = 0; l < NLAYER; l++) {
        // QKV: three [8192,512]x[512,512] GEMMs into strided qkv buffer (ldc = 1536)
        for (int j = 0; j < 3; j++) {
            sgemm_kernel<false, false><<<gN512, 256>>>(
                h, Wqkv + (size_t)(l * 3 + j) * DM * DM, bqkv + (size_t)(l * 3 + j) * DM,
                nullptr, qkv + j * DM, TOKENS, DM, DM, DM, 3 * DM);
        }
        attn_kernel<<<32, 64>>>(qkv, attn);
        // h = h + attn @ Wo + bo   (residual fused)
        sgemm_kernel<false, true><<<gN512, 256>>>(
            attn, Wo + (size_t)l * DM * DM, bo + (size_t)l * DM,
            h, h, TOKENS, DM, DM, DM, DM);
        ln_kernel<<<TOKENS, 128>>>(h, ln1g + l * DM, ln1b + l * DM, h);
        // ff = relu(h @ W1 + b1)
        sgemm_kernel<true, false><<<gN2048, 256>>>(
            h, W1 + (size_t)l * DM * DFF, b1 + (size_t)l * DFF,
            nullptr, ff, TOKENS, DFF, DM, DFF, DFF);
        // h = h + ff @ W2 + b2
        sgemm_kernel<false, true><<<gN512, 256>>>(
            ff, W2 + (size_t)l * DFF * DM, b2 + (size_t)l * DM,
            h, h, TOKENS, DM, DFF, DM, DM);
        ln_kernel<<<TOKENS, 128>>>(h, ln2g + l * DM, ln2b + l * DM, h);
    }

    ln_kernel<<<TOKENS, 128>>>(h, lnfg, lnfb, h);
    sgemm_kernel<false, false><<<gNout, 256>>>(
        h, Wout, bout, nullptr, out, TOKENS, NVOCAB, DM, NVOCAB, NVOCAB);
}

// round 3
// speedup vs baseline: 1.5293x; 1.5293x over previous
#include <cuda_runtime.h>
#include <cuda_bf16.h>
#include <cmath>

#define TOKENS 8192
#define SEQ 2048
#define DM 512
#define DFF 2048
#define NLAYER 12
#define NVOCAB 400

// ---------------- scratch (device globals: allocation-guard safe) ----------------
__device__ float g_h[TOKENS * DM];
__device__ float g_qkv[TOKENS * 3 * DM];
__device__ float g_attn[TOKENS * DM];
__device__ float g_ff[TOKENS * DFF];

static __device__ __forceinline__ unsigned sptr(const void* p) {
    return (unsigned)__cvta_generic_to_shared(p);
}

// split two floats into packed bf16 hi pair and bf16 lo (residual) pair
static __device__ __forceinline__ void split2(float x, float y,
                                              unsigned& hi, unsigned& lo)
{
    __nv_bfloat162 h = __floats2bfloat162_rn(x, y);
    float rx = x - __bfloat162float(h.x);
    float ry = y - __bfloat162float(h.y);
    __nv_bfloat162 l = __floats2bfloat162_rn(rx, ry);
    hi = *reinterpret_cast<unsigned*>(&h);
    lo = *reinterpret_cast<unsigned*>(&l);
}

// ---------------- embedding + sinusoidal PE ----------------
__global__ void embed_kernel(const int* __restrict__ x, const float* __restrict__ emb,
                             float* __restrict__ h)
{
    int t = blockIdx.x;
    int s = t & (SEQ - 1);
    int tok = x[t];
    const float C1 = -9.210340371976184f / 512.0f;
    for (int d = threadIdx.x; d < DM; d += blockDim.x) {
        int p = d >> 1;
        float div = expf((float)(2 * p) * C1);
        float ang = (float)s * div;
        float pe = (d & 1) ? cosf(ang) : sinf(ang);
        h[(size_t)t * DM + d] = emb[(size_t)tok * DM + d] * 22.62741699796952f + pe;
    }
}

// ---------------- LayerNorm ----------------
__global__ void __launch_bounds__(128) ln_kernel(const float* __restrict__ in,
                                                 const float* __restrict__ g,
                                                 const float* __restrict__ b,
                                                 float* __restrict__ out)
{
    __shared__ float sh[8];
    int row = blockIdx.x;
    int t = threadIdx.x;
    float4 x = ((const float4*)(in + (size_t)row * DM))[t];

    float s = x.x + x.y + x.z + x.w;
    #pragma unroll
    for (int o = 16; o > 0; o >>= 1) s += __shfl_xor_sync(0xffffffffu, s, o);
    if ((t & 31) == 0) sh[t >> 5] = s;
    __syncthreads();
    float mean = (sh[0] + sh[1] + sh[2] + sh[3]) * (1.0f / DM);

    float dx = x.x - mean, dy = x.y - mean, dz = x.z - mean, dw = x.w - mean;
    float sq = dx * dx + dy * dy + dz * dz + dw * dw;
    #pragma unroll
    for (int o = 16; o > 0; o >>= 1) sq += __shfl_xor_sync(0xffffffffu, sq, o);
    if ((t & 31) == 0) sh[4 + (t >> 5)] = sq;
    __syncthreads();
    float var = (sh[4] + sh[5] + sh[6] + sh[7]) * (1.0f / DM);
    float rs = rsqrtf(var + 1e-5f);

    float4 gg = ((const float4*)g)[t];
    float4 bb = ((const float4*)b)[t];
    float4 o4;
    o4.x = dx * rs * gg.x + bb.x;
    o4.y = dy * rs * gg.y + bb.y;
    o4.z = dz * rs * gg.z + bb.z;
    o4.w = dw * rs * gg.w + bb.w;
    ((float4*)(out + (size_t)row * DM))[t] = o4;
}

// ---------------- causal linear attention (unchanged, verified) ----------------
__global__ void __launch_bounds__(64) attn_kernel(const float* __restrict__ qkv,
                                                  float* __restrict__ out)
{
    int b = blockIdx.x >> 3;
    int hh = blockIdx.x & 7;
    int e = threadIdx.x;

    __shared__ float ks[32][64];
    __shared__ float qs[32][64];
    __shared__ float vs[32][64];
    __shared__ float ps[32][65];
    __shared__ float dens[32];

    float S[64];
    #pragma unroll
    for (int d = 0; d < 64; d++) S[d] = 0.0f;
    float zc = 0.0f;

    const float* base = qkv + (size_t)b * SEQ * (3 * DM) + hh * 64;
    float* ob = out + (size_t)b * SEQ * DM + hh * 64;

    for (int c0 = 0; c0 < SEQ; c0 += 32) {
        #pragma unroll 4
        for (int j = 0; j < 32; j++) {
            const float* r = base + (size_t)(c0 + j) * (3 * DM);
            float qv = r[e], kv = r[DM + e], vv = r[2 * DM + e];
            qs[j][e] = (qv > 0.0f) ? qv + 1.0f : expf(qv);
            ks[j][e] = (kv > 0.0f) ? kv + 1.0f : expf(kv);
            vs[j][e] = vv;
        }
        __syncthreads();

        float z = zc;
        #pragma unroll
        for (int j = 0; j < 32; j++) { z += ks[j][e]; ps[j][e] = qs[j][e] * z; }
        zc = z;
        __syncthreads();

        if (e < 32) {
            float sum = 0.0f;
            #pragma unroll 8
            for (int d = 0; d < 64; d++) sum += ps[e][d];
            dens[e] = sum + 1e-6f;
        }
        __syncthreads();

        for (int j = 0; j < 32; j++) {
            float ve = vs[j][e];
            float n0 = 0.f, n1 = 0.f, n2 = 0.f, n3 = 0.f;
            #pragma unroll
            for (int d = 0; d < 64; d += 4) {
                S[d + 0] = fmaf(ks[j][d + 0], ve, S[d + 0]); n0 = fmaf(qs[j][d + 0], S[d + 0], n0);
                S[d + 1] = fmaf(ks[j][d + 1], ve, S[d + 1]); n1 = fmaf(qs[j][d + 1], S[d + 1], n1);
                S[d + 2] = fmaf(ks[j][d + 2], ve, S[d + 2]); n2 = fmaf(qs[j][d + 2], S[d + 2], n2);
                S[d + 3] = fmaf(ks[j][d + 3], ve, S[d + 3]); n3 = fmaf(qs[j][d + 3], S[d + 3], n3);
            }
            ob[(size_t)(c0 + j) * DM + e] = ((n0 + n1) + (n2 + n3)) / dens[j];
        }
        __syncthreads();
    }
}

// ================= bf16x3 error-compensated tensor GEMM =================
// C[M,N] = A[M,K] @ B[K,N] + bias (+Res) (relu?)   -- near-fp32 accuracy.
// A,B split into bf16 hi + bf16 lo (residual); acc += hi*hi + hi*lo + lo*hi.
// 128x128x32 block tile, 256 threads, warps 2(m)x4(n), warp tile 64x32,
// mma.sync.m16n8k16.bf16, double-buffered smem (reg-staged conversion).
// Chunked-B columns for fused QKV. Requires M%128==0, N%128==0, K%32==0.
#define ASB 72        // A smem row stride (bf16): hi cols 0..31, lo 32..63, pad
#define BSB 264       // B smem row stride (bf16): hi cols 0..127, lo 128..255, pad
#define AS_E (128 * ASB)
#define BS_E (32 * BSB)
#define TG_SMEM ((AS_E + BS_E) * 2 * 2)   // 2 buffers, 2 bytes/elem

#define MMA_BF16(d, a, b) \
    asm volatile("mma.sync.aligned.m16n8k16.row.col.f32.bf16.bf16.f32 " \
                 "{%0,%1,%2,%3},{%4,%5,%6,%7},{%8,%9},{%0,%1,%2,%3};" \
                 : "+f"((d)[0]), "+f"((d)[1]), "+f"((d)[2]), "+f"((d)[3]) \
                 : "r"((a)[0]), "r"((a)[1]), "r"((a)[2]), "r"((a)[3]), \
                   "r"((b)[0]), "r"((b)[1]))

template <bool RELU, bool RES>
__global__ void __launch_bounds__(256) tgemm_kernel(
    const float* __restrict__ A, const float* __restrict__ B,
    const float* __restrict__ bias, const float* __restrict__ Res,
    float* __restrict__ C, int M, int N, int K,
    int ldb, int nPerChunk, size_t chunkStride, int ldc)
{
    extern __shared__ __align__(16) unsigned char smem_raw[];
    __nv_bfloat16* As = (__nv_bfloat16*)smem_raw;
    __nv_bfloat16* Bs = As + 2 * AS_E;

    int tid = threadIdx.x;
    int m0 = blockIdx.y * 128;
    int n0 = blockIdx.x * 128;
    int chunk = n0 / nPerChunk;
    const float* Bb = B + (size_t)chunk * chunkStride + (n0 % nPerChunk);

    // staging coords
    int ar = tid >> 3, ac = (tid & 7) << 2;    // A: 32 rows/pass x 32 k-cols
    int br = tid >> 5, bc = (tid & 31) << 2;   // B: 8 k-rows/pass x 128 n-cols
    const float* Ag = A + (size_t)(m0 + ar) * K + ac;
    const float* Bg = Bb + (size_t)br * ldb + bc;

    int warp = tid >> 5, lane = tid & 31;
    int wm = (warp >> 2) * 64, wn = (warp & 3) * 32;
    int g = lane >> 2, ctg = lane & 3;
    int lrow = lane & 15, lcol8 = (lane >> 4) * 8;

    float acc[4][4][4];
    #pragma unroll
    for (int i = 0; i < 4; i++)
        #pragma unroll
        for (int j = 0; j < 4; j++)
            #pragma unroll
            for (int r = 0; r < 4; r++) acc[i][j][r] = 0.0f;

    int nt = K / 32;
    float4 aR[4], bR[4];

    // ---- prologue: load + convert tile 0 into buffer 0 ----
    #pragma unroll
    for (int p = 0; p < 4; p++) {
        aR[p] = *(const float4*)(Ag + (size_t)(32 * p) * K);
        bR[p] = *(const float4*)(Bg + (size_t)(8 * p) * ldb);
    }
    #pragma unroll
    for (int p = 0; p < 4; p++) {
        unsigned h0, l0, h1, l1;
        split2(aR[p].x, aR[p].y, h0, l0);
        split2(aR[p].z, aR[p].w, h1, l1);
        unsigned* dh = (unsigned*)(As + (ar + 32 * p) * ASB + ac);
        unsigned* dl = (unsigned*)(As + (ar + 32 * p) * ASB + 32 + ac);
        dh[0] = h0; dh[1] = h1; dl[0] = l0; dl[1] = l1;
        split2(bR[p].x, bR[p].y, h0, l0);
        split2(bR[p].z, bR[p].w, h1, l1);
        dh = (unsigned*)(Bs + (br + 8 * p) * BSB + bc);
        dl = (unsigned*)(Bs + (br + 8 * p) * BSB + 128 + bc);
        dh[0] = h0; dh[1] = h1; dl[0] = l0; dl[1] = l1;
    }
    __syncthreads();

    for (int kt = 0; kt < nt; kt++) {
        // issue global loads for next tile (hide under MMAs)
        if (kt + 1 < nt) {
            #pragma unroll
            for (int p = 0; p < 4; p++) {
                aR[p] = *(const float4*)(Ag + (size_t)(32 * p) * K + (kt + 1) * 32);
                bR[p] = *(const float4*)(Bg + (size_t)((kt + 1) * 32 + 8 * p) * ldb);
            }
        }

        const __nv_bfloat16* as = As + (kt & 1) * AS_E;
        const __nv_bfloat16* bs = Bs + (kt & 1) * BS_E;

        #pragma unroll
        for (int ks = 0; ks < 32; ks += 16) {
            // B fragments: hi and lo, 4 n8-tiles
            unsigned bh[4][2], bl[4][2];
            #pragma unroll
            for (int nj = 0; nj < 2; nj++) {
                unsigned addr = sptr(bs + (ks + lrow) * BSB + wn + 16 * nj + lcol8);
                unsigned t0, t1, t2, t3;
                asm volatile("ldmatrix.sync.aligned.m8n8.x4.trans.shared.b16 "
                             "{%0,%1,%2,%3}, [%4];"
                             : "=r"(t0), "=r"(t1), "=r"(t2), "=r"(t3) : "r"(addr));
                bh[2 * nj][0] = t0; bh[2 * nj][1] = t1;
                bh[2 * nj + 1][0] = t2; bh[2 * nj + 1][1] = t3;
                asm volatile("ldmatrix.sync.aligned.m8n8.x4.trans.shared.b16 "
                             "{%0,%1,%2,%3}, [%4];"
                             : "=r"(t0), "=r"(t1), "=r"(t2), "=r"(t3)
                             : "r"(addr + 256));   // +128 bf16 cols
                bl[2 * nj][0] = t0; bl[2 * nj][1] = t1;
                bl[2 * nj + 1][0] = t2; bl[2 * nj + 1][1] = t3;
            }
            #pragma unroll
            for (int i = 0; i < 4; i++) {
                unsigned ah[4], al[4];
                unsigned addr = sptr(as + (wm + 16 * i + lrow) * ASB + ks + lcol8);
                asm volatile("ldmatrix.sync.aligned.m8n8.x4.shared.b16 "
                             "{%0,%1,%2,%3}, [%4];"
                             : "=r"(ah[0]), "=r"(ah[1]), "=r"(ah[2]), "=r"(ah[3])
                             : "r"(addr));
                asm volatile("ldmatrix.sync.aligned.m8n8.x4.shared.b16 "
                             "{%0,%1,%2,%3}, [%4];"
                             : "=r"(al[0]), "=r"(al[1]), "=r"(al[2]), "=r"(al[3])
                             : "r"(addr + 64));    // +32 bf16 cols
                #pragma unroll
                for (int j = 0; j < 4; j++) {
                    MMA_BF16(acc[i][j], ah, bh[j]);
                    MMA_BF16(acc[i][j], ah, bl[j]);
                    MMA_BF16(acc[i][j], al, bh[j]);
                }
            }
        }

        // convert + store next tile into the other buffer
        if (kt + 1 < nt) {
            __nv_bfloat16* asn = As + ((kt + 1) & 1) * AS_E;
            __nv_bfloat16* bsn = Bs + ((kt + 1) & 1) * BS_E;
            #pragma unroll
            for (int p = 0; p < 4; p++) {
                unsigned h0, l0, h1, l1;
                split2(aR[p].x, aR[p].y, h0, l0);
                split2(aR[p].z, aR[p].w, h1, l1);
                unsigned* dh = (unsigned*)(asn + (ar + 32 * p) * ASB + ac);
                unsigned* dl = (unsigned*)(asn + (ar + 32 * p) * ASB + 32 + ac);
                dh[0] = h0; dh[1] = h1; dl[0] = l0; dl[1] = l1;
                split2(bR[p].x, bR[p].y, h0, l0);
                split2(bR[p].z, bR[p].w, h1, l1);
                dh = (unsigned*)(bsn + (br + 8 * p) * BSB + bc);
                dl = (unsigned*)(bsn + (br + 8 * p) * BSB + 128 + bc);
                dh[0] = h0; dh[1] = h1; dl[0] = l0; dl[1] = l1;
            }
        }
        __syncthreads();
    }

    // ---- epilogue: bias (+res) (relu) ----
    #pragma unroll
    for (int i = 0; i < 4; i++) {
        int mrow = m0 + wm + 16 * i + g;
        #pragma unroll
        for (int j = 0; j < 4; j++) {
            int n = n0 + wn + 8 * j + 2 * ctg;
            float2 bv = *(const float2*)(bias + n);
            float v0 = acc[i][j][0] + bv.x, v1 = acc[i][j][1] + bv.y;
            float v2 = acc[i][j][2] + bv.x, v3 = acc[i][j][3] + bv.y;
            if (RES) {
                float2 r0 = *(const float2*)(Res + (size_t)mrow * ldc + n);
                float2 r1 = *(const float2*)(Res + (size_t)(mrow + 8) * ldc + n);
                v0 += r0.x; v1 += r0.y; v2 += r1.x; v3 += r1.y;
            }
            if (RELU) {
                v0 = fmaxf(v0, 0.0f); v1 = fmaxf(v1, 0.0f);
                v2 = fmaxf(v2, 0.0f); v3 = fmaxf(v3, 0.0f);
            }
            *(float2*)(C + (size_t)mrow * ldc + n) = make_float2(v0, v1);
            *(float2*)(C + (size_t)(mrow + 8) * ldc + n) = make_float2(v2, v3);
        }
    }
}

// ---------------- fp32 fallback GEMM (out-projection, N=400 with guards) ----------------
template <bool RELU, bool RES>
__global__ void __launch_bounds__(256) sgemm_kernel(
    const float* __restrict__ A, const float* __restrict__ B,
    const float* __restrict__ bias, const float* __restrict__ Res,
    float* __restrict__ C, int M, int N, int K, int ldb, int ldc)
{
    __shared__ float As[16][128];
    __shared__ float Bs[16][128];

    int tid = threadIdx.x;
    int m0 = blockIdx.y * 128;
    int n0 = blockIdx.x * 128;
    bool fullN = (n0 + 128 <= N);

    float acc[8][8];
    #pragma unroll
    for (int i = 0; i < 8; i++)
        #pragma unroll
        for (int j = 0; j < 8; j++) acc[i][j] = 0.0f;

    int a_r = tid >> 2, a_c = (tid & 3) << 2;
    int b_r = tid >> 5, b_c = (tid & 31) << 2;
    int mm = (tid >> 4) << 3;
    int nn = (tid & 15) << 3;

    for (int kt = 0; kt < K; kt += 16) {
        #pragma unroll
        for (int p = 0; p < 2; p++) {
            int r = a_r + p * 64;
            float4 f = *(const float4*)(A + (size_t)(m0 + r) * K + kt + a_c);
            As[a_c + 0][r] = f.x; As[a_c + 1][r] = f.y;
            As[a_c + 2][r] = f.z; As[a_c + 3][r] = f.w;
        }
        #pragma unroll
        for (int p = 0; p < 2; p++) {
            int r = b_r + p * 8;
            const float* src = B + (size_t)(kt + r) * ldb + n0 + b_c;
            float4 f;
            if (fullN) {
                f = *(const float4*)src;
            } else {
                f.x = (n0 + b_c + 0 < N) ? src[0] : 0.0f;
                f.y = (n0 + b_c + 1 < N) ? src[1] : 0.0f;
                f.z = (n0 + b_c + 2 < N) ? src[2] : 0.0f;
                f.w = (n0 + b_c + 3 < N) ? src[3] : 0.0f;
            }
            *(float4*)(&Bs[r][b_c]) = f;
        }
        __syncthreads();

        #pragma unroll
        for (int k = 0; k < 16; k++) {
            float a[8], bb[8];
            *(float4*)(a)      = *(const float4*)(&As[k][mm]);
            *(float4*)(a + 4)  = *(const float4*)(&As[k][mm + 4]);
            *(float4*)(bb)     = *(const float4*)(&Bs[k][nn]);
            *(float4*)(bb + 4) = *(const float4*)(&Bs[k][nn + 4]);
            #pragma unroll
            for (int i = 0; i < 8; i++)
                #pragma unroll
                for (int j = 0; j < 8; j++)
                    acc[i][j] = fmaf(a[i], bb[j], acc[i][j]);
        }
        __syncthreads();
    }

    #pragma unroll
    for (int i = 0; i < 8; i++) {
        int m = m0 + mm + i;
        #pragma unroll
        for (int j = 0; j < 8; j++) {
            int n = nn + n0 + j;
            if (n < N) {
                float v = acc[i][j] + bias[n];
                if (RES) v += Res[(size_t)m * ldc + n];
                if (RELU) v = fmaxf(v, 0.0f);
                C[(size_t)m * ldc + n] = v;
            }
        }
    }
}

// ---------------- launch ----------------
extern "C" void kernel_launch(void* const* d_in, const int* in_sizes, int n_in,
                              void* d_out, int out_size)
{
    const int*   x    = (const int*)d_in[0];
    const float* emb  = (const float*)d_in[1];
    const float* Wqkv = (const float*)d_in[2];
    const float* bqkv = (const float*)d_in[3];
    const float* Wo   = (const float*)d_in[4];
    const float* bo   = (const float*)d_in[5];
    const float* ln1g = (const float*)d_in[6];
    const float* ln1b = (const float*)d_in[7];
    const float* W1   = (const float*)d_in[8];
    const float* b1   = (const float*)d_in[9];
    const float* W2   = (const float*)d_in[10];
    const float* b2   = (const float*)d_in[11];
    const float* ln2g = (const float*)d_in[12];
    const float* ln2b = (const float*)d_in[13];
    const float* lnfg = (const float*)d_in[14];
    const float* lnfb = (const float*)d_in[15];
    const float* Wout = (const float*)d_in[16];
    const float* bout = (const float*)d_in[17];
    float* out = (float*)d_out;

    float *h, *qkv, *attn, *ff;
    cudaGetSymbolAddress((void**)&h,    g_h);
    cudaGetSymbolAddress((void**)&qkv,  g_qkv);
    cudaGetSymbolAddress((void**)&attn, g_attn);
    cudaGetSymbolAddress((void**)&ff,   g_ff);

    cudaFuncSetAttribute(tgemm_kernel<false, false>,
                         cudaFuncAttributeMaxDynamicSharedMemorySize, TG_SMEM);
    cudaFuncSetAttribute(tgemm_kernel<false, true>,
                         cudaFuncAttributeMaxDynamicSharedMemorySize, TG_SMEM);
    cudaFuncSetAttribute(tgemm_kernel<true, false>,
                         cudaFuncAttributeMaxDynamicSharedMemorySize, TG_SMEM);

    embed_kernel<<<TOKENS, 128>>>(x, emb, h);

    dim3 gQKV(12, TOKENS / 128);    // N = 1536 (Q,K,V fused via chunked B)
    dim3 gN512(4, TOKENS / 128);
    dim3 gN2048(16, TOKENS / 128);
    dim3 gNout((NVOCAB + 127) / 128, TOKENS / 128);

    for (int l = 0; l < NLAYER; l++) {
        tgemm_kernel<false, false><<<gQKV, 256, TG_SMEM>>>(
            h, Wqkv + (size_t)l * 3 * DM * DM, bqkv + (size_t)l * 3 * DM,
            nullptr, qkv, TOKENS, 3 * DM, DM,
            DM, DM, (size_t)DM * DM, 3 * DM);

        attn_kernel<<<32, 64>>>(qkv, attn);

        tgemm_kernel<false, true><<<gN512, 256, TG_SMEM>>>(
            attn, Wo + (size_t)l * DM * DM, bo + (size_t)l * DM,
            h, h, TOKENS, DM, DM,
            DM, DM, 0, DM);
        ln_kernel<<<TOKENS, 128>>>(h, ln1g + l * DM, ln1b + l * DM, h);

        tgemm_kernel<true, false><<<gN2048, 256, TG_SMEM>>>(
            h, W1 + (size_t)l * DM * DFF, b1 + (size_t)l * DFF,
            nullptr, ff, TOKENS, DFF, DM,
            DFF, DFF, 0, DFF);

        tgemm_kernel<false, true><<<gN512, 256, TG_SMEM>>>(
            ff, W2 + (size_t)l * DFF * DM, b2 + (size_t)l * DM,
            h, h, TOKENS, DM, DFF,
            DM, DM, 0, DM);
        ln_kernel<<<TOKENS, 128>>>(h, ln2g + l * DM, ln2b + l * DM, h);
    }

    ln_kernel<<<TOKENS, 128>>>(h, lnfg, lnfb, h);
    sgemm_kernel<false, false><<<gNout, 256>>>(
        h, Wout, bout, nullptr, out, TOKENS, NVOCAB, DM, NVOCAB, NVOCAB);
}

// round 4
// speedup vs baseline: 3.5664x; 2.3321x over previous
#include <cuda_runtime.h>
#include <cuda_bf16.h>
#include <cmath>

#define TOKENS 8192
#define SEQ 2048
#define DM 512
#define DFF 2048
#define NLAYER 12
#define NVOCAB 400
#define NP 16          // attention partitions
#define PLEN 128       // steps per partition

typedef __nv_bfloat16 bf16;

// ---------------- scratch (device globals) ----------------
__device__ float g_h[TOKENS * DM];
__device__ float g_qkv[TOKENS * 3 * DM];
__device__ bf16  g_h_hi[TOKENS * DM];
__device__ bf16  g_h_lo[TOKENS * DM];
__device__ bf16  g_attn_hi[TOKENS * DM];
__device__ bf16  g_attn_lo[TOKENS * DM];
__device__ bf16  g_ff_hi[TOKENS * DFF];
__device__ bf16  g_ff_lo[TOKENS * DFF];
// split weights: qkv | wo | w1 | w2
#define OFF_QKV 0
#define OFF_WO  (NLAYER * 3 * DM * DM)                    // 9437184
#define OFF_W1  (OFF_WO + NLAYER * DM * DM)               // 12582912
#define OFF_W2  (OFF_W1 + NLAYER * DM * DFF)              // 25165824
#define W_TOTAL (OFF_W2 + NLAYER * DFF * DM)              // 37748736
__device__ bf16 g_w_hi[W_TOTAL];
__device__ bf16 g_w_lo[W_TOTAL];
// attention partial states
__device__ float g_state[32 * NP * 64 * 64];  // 8 MB
__device__ float g_z[32 * NP * 64];

static __device__ __forceinline__ unsigned sptr(const void* p) {
    return (unsigned)__cvta_generic_to_shared(p);
}

static __device__ __forceinline__ void split2(float x, float y,
                                              unsigned& hi, unsigned& lo)
{
    __nv_bfloat162 h = __floats2bfloat162_rn(x, y);
    float rx = x - __bfloat162float(h.x);
    float ry = y - __bfloat162float(h.y);
    __nv_bfloat162 l = __floats2bfloat162_rn(rx, ry);
    hi = *reinterpret_cast<unsigned*>(&h);
    lo = *reinterpret_cast<unsigned*>(&l);
}

// ---------------- weight split: fp32 -> bf16 hi/lo ----------------
__global__ void __launch_bounds__(256) split_kernel(const float* __restrict__ src,
                                                    bf16* __restrict__ hi,
                                                    bf16* __restrict__ lo, int n4)
{
    int i = blockIdx.x * 256 + threadIdx.x;
    if (i >= n4) return;
    float4 f = ((const float4*)src)[i];
    unsigned h0, l0, h1, l1;
    split2(f.x, f.y, h0, l0);
    split2(f.z, f.w, h1, l1);
    ((uint2*)hi)[i] = make_uint2(h0, h1);
    ((uint2*)lo)[i] = make_uint2(l0, l1);
}

// ---------------- embedding + PE (+ hi/lo) ----------------
__global__ void embed_kernel(const int* __restrict__ x, const float* __restrict__ emb,
                             float* __restrict__ h, bf16* __restrict__ hhi,
                             bf16* __restrict__ hlo)
{
    int t = blockIdx.x;
    int s = t & (SEQ - 1);
    int tok = x[t];
    const float C1 = -9.210340371976184f / 512.0f;
    for (int d = threadIdx.x; d < DM; d += blockDim.x) {
        int p = d >> 1;
        float div = expf((float)(2 * p) * C1);
        float ang = (float)s * div;
        float pe = (d & 1) ? cosf(ang) : sinf(ang);
        float v = emb[(size_t)tok * DM + d] * 22.62741699796952f + pe;
        h[(size_t)t * DM + d] = v;
        bf16 hv = __float2bfloat16(v);
        hhi[(size_t)t * DM + d] = hv;
        hlo[(size_t)t * DM + d] = __float2bfloat16(v - __bfloat162float(hv));
    }
}

// ---------------- LayerNorm (+ optional hi/lo) ----------------
__global__ void __launch_bounds__(128) ln_kernel(const float* __restrict__ in,
                                                 const float* __restrict__ g,
                                                 const float* __restrict__ b,
                                                 float* __restrict__ out,
                                                 bf16* __restrict__ ohi,
                                                 bf16* __restrict__ olo)
{
    __shared__ float sh[8];
    int row = blockIdx.x;
    int t = threadIdx.x;
    float4 x = ((const float4*)(in + (size_t)row * DM))[t];

    float s = x.x + x.y + x.z + x.w;
    #pragma unroll
    for (int o = 16; o > 0; o >>= 1) s += __shfl_xor_sync(0xffffffffu, s, o);
    if ((t & 31) == 0) sh[t >> 5] = s;
    __syncthreads();
    float mean = (sh[0] + sh[1] + sh[2] + sh[3]) * (1.0f / DM);

    float dx = x.x - mean, dy = x.y - mean, dz = x.z - mean, dw = x.w - mean;
    float sq = dx * dx + dy * dy + dz * dz + dw * dw;
    #pragma unroll
    for (int o = 16; o > 0; o >>= 1) sq += __shfl_xor_sync(0xffffffffu, sq, o);
    if ((t & 31) == 0) sh[4 + (t >> 5)] = sq;
    __syncthreads();
    float var = (sh[4] + sh[5] + sh[6] + sh[7]) * (1.0f / DM);
    float rs = rsqrtf(var + 1e-5f);

    float4 gg = ((const float4*)g)[t];
    float4 bb = ((const float4*)b)[t];
    float4 o4;
    o4.x = dx * rs * gg.x + bb.x;
    o4.y = dy * rs * gg.y + bb.y;
    o4.z = dz * rs * gg.z + bb.z;
    o4.w = dw * rs * gg.w + bb.w;
    ((float4*)(out + (size_t)row * DM))[t] = o4;
    if (ohi) {
        unsigned h0, l0, h1, l1;
        split2(o4.x, o4.y, h0, l0);
        split2(o4.z, o4.w, h1, l1);
        ((uint2*)(ohi + (size_t)row * DM))[t] = make_uint2(h0, h1);
        ((uint2*)(olo + (size_t)row * DM))[t] = make_uint2(l0, l1);
    }
}

// ---------------- attention pass 1: per-partition K^T V sums + z sums ----------------
__global__ void __launch_bounds__(64) attn_sums_kernel(const float* __restrict__ qkv,
                                                       float* __restrict__ state,
                                                       float* __restrict__ zbuf)
{
    int bh = blockIdx.x, p = blockIdx.y;
    int b = bh >> 3, hh = bh & 7;
    int e = threadIdx.x;

    __shared__ float ks[32][64];
    __shared__ float vs[32][64];

    float S[64];
    #pragma unroll
    for (int d = 0; d < 64; d++) S[d] = 0.0f;
    float zc = 0.0f;

    const float* base = qkv + (size_t)b * SEQ * (3 * DM) + hh * 64;

    for (int c0 = p * PLEN; c0 < p * PLEN + PLEN; c0 += 32) {
        #pragma unroll 4
        for (int j = 0; j < 32; j++) {
            const float* r = base + (size_t)(c0 + j) * (3 * DM);
            float kv = r[DM + e], vv = r[2 * DM + e];
            ks[j][e] = (kv > 0.0f) ? kv + 1.0f : expf(kv);
            vs[j][e] = vv;
        }
        __syncthreads();
        for (int j = 0; j < 32; j++) {
            float ve = vs[j][e];
            zc += ks[j][e];
            #pragma unroll
            for (int d = 0; d < 64; d++) S[d] = fmaf(ks[j][d], ve, S[d]);
        }
        __syncthreads();
    }

    float* st = state + ((size_t)bh * NP + p) * 4096;
    #pragma unroll 4
    for (int d = 0; d < 64; d++) st[d * 64 + e] = S[d];
    zbuf[((size_t)bh * NP + p) * 64 + e] = zc;
}

// ---------------- attention pass 2: in-place exclusive prefix over partitions ----------------
__global__ void __launch_bounds__(256) attn_prefix_kernel(float* __restrict__ state,
                                                          float* __restrict__ zbuf)
{
    int bh = blockIdx.x;
    int e = threadIdx.x & 63;
    int dg = threadIdx.x >> 6;   // 4 groups of 16 d's

    float acc[16];
    #pragma unroll
    for (int i = 0; i < 16; i++) acc[i] = 0.0f;
    float zacc = 0.0f;

    for (int p = 0; p < NP; p++) {
        float* st = state + ((size_t)bh * NP + p) * 4096;
        #pragma unroll
        for (int i = 0; i < 16; i++) {
            int d = dg * 16 + i;
            float t = st[d * 64 + e];
            st[d * 64 + e] = acc[i];
            acc[i] += t;
        }
        if (dg == 0) {
            float* z = zbuf + ((size_t)bh * NP + p) * 64;
            float t = z[e];
            z[e] = zacc;
            zacc += t;
        }
    }
}

// ---------------- attention pass 3: scan per partition with init state ----------------
__global__ void __launch_bounds__(64) attn_scan_kernel(const float* __restrict__ qkv,
                                                       const float* __restrict__ state,
                                                       const float* __restrict__ zbuf,
                                                       bf16* __restrict__ ohi,
                                                       bf16* __restrict__ olo)
{
    int bh = blockIdx.x, p = blockIdx.y;
    int b = bh >> 3, hh = bh & 7;
    int e = threadIdx.x;

    __shared__ float ks[32][64];
    __shared__ float qs[32][64];
    __shared__ float vs[32][64];
    __shared__ float ps[32][65];
    __shared__ float dens[32];

    float S[64];
    const float* st = state + ((size_t)bh * NP + p) * 4096;
    #pragma unroll 4
    for (int d = 0; d < 64; d++) S[d] = st[d * 64 + e];
    float zc = zbuf[((size_t)bh * NP + p) * 64 + e];

    const float* base = qkv + (size_t)b * SEQ * (3 * DM) + hh * 64;
    size_t obase = (size_t)b * SEQ * DM + hh * 64 + e;

    for (int c0 = p * PLEN; c0 < p * PLEN + PLEN; c0 += 32) {
        #pragma unroll 4
        for (int j = 0; j < 32; j++) {
            const float* r = base + (size_t)(c0 + j) * (3 * DM);
            float qv = r[e], kv = r[DM + e], vv = r[2 * DM + e];
            qs[j][e] = (qv > 0.0f) ? qv + 1.0f : expf(qv);
            ks[j][e] = (kv > 0.0f) ? kv + 1.0f : expf(kv);
            vs[j][e] = vv;
        }
        __syncthreads();

        float z = zc;
        #pragma unroll
        for (int j = 0; j < 32; j++) { z += ks[j][e]; ps[j][e] = qs[j][e] * z; }
        zc = z;
        __syncthreads();

        if (e < 32) {
            float sum = 0.0f;
            #pragma unroll 8
            for (int d = 0; d < 64; d++) sum += ps[e][d];
            dens[e] = sum + 1e-6f;
        }
        __syncthreads();

        for (int j = 0; j < 32; j++) {
            float ve = vs[j][e];
            float n0 = 0.f, n1 = 0.f, n2 = 0.f, n3 = 0.f;
            #pragma unroll
            for (int d = 0; d < 64; d += 4) {
                S[d + 0] = fmaf(ks[j][d + 0], ve, S[d + 0]); n0 = fmaf(qs[j][d + 0], S[d + 0], n0);
                S[d + 1] = fmaf(ks[j][d + 1], ve, S[d + 1]); n1 = fmaf(qs[j][d + 1], S[d + 1], n1);
                S[d + 2] = fmaf(ks[j][d + 2], ve, S[d + 2]); n2 = fmaf(qs[j][d + 2], S[d + 2], n2);
                S[d + 3] = fmaf(ks[j][d + 3], ve, S[d + 3]); n3 = fmaf(qs[j][d + 3], S[d + 3], n3);
            }
            float o = ((n0 + n1) + (n2 + n3)) / dens[j];
            bf16 hv = __float2bfloat16(o);
            size_t idx = obase + (size_t)(c0 + j) * DM;
            ohi[idx] = hv;
            olo[idx] = __float2bfloat16(o - __bfloat162float(hv));
        }
        __syncthreads();
    }
}

// ================= bf16x3 tensor GEMM, pre-split operands =================
// C = (Ahi+Alo)[M,K] @ (Bhi+Blo)[K,N] + bias (+Res) (relu?), hi*hi+hi*lo+lo*hi.
// 128x128x32 tile, 256 threads, warps 2x4, warp tile 64x32, m16n8k16 bf16.
#define ASB 72
#define BSB 264
#define AS_E (128 * ASB)
#define BS_E (32 * BSB)
#define TG_SMEM ((AS_E + BS_E) * 2 * 2)

#define MMA_BF16(d, a, b) \
    asm volatile("mma.sync.aligned.m16n8k16.row.col.f32.bf16.bf16.f32 " \
                 "{%0,%1,%2,%3},{%4,%5,%6,%7},{%8,%9},{%0,%1,%2,%3};" \
                 : "+f"((d)[0]), "+f"((d)[1]), "+f"((d)[2]), "+f"((d)[3]) \
                 : "r"((a)[0]), "r"((a)[1]), "r"((a)[2]), "r"((a)[3]), \
                   "r"((b)[0]), "r"((b)[1]))

template <bool RELU, bool RES, bool WF32, bool WBF>
__global__ void __launch_bounds__(256, 2) tgemm_kernel(
    const bf16* __restrict__ Ahi, const bf16* __restrict__ Alo,
    const bf16* __restrict__ Bhi, const bf16* __restrict__ Blo,
    const float* __restrict__ bias, const float* __restrict__ Res,
    float* __restrict__ C, bf16* __restrict__ Chi, bf16* __restrict__ Clo,
    int M, int N, int K, int ldb, int nPerChunk, size_t chunkStride, int ldc)
{
    extern __shared__ __align__(16) unsigned char smem_raw[];
    bf16* As = (bf16*)smem_raw;
    bf16* Bs = As + 2 * AS_E;

    int tid = threadIdx.x;
    int m0 = blockIdx.y * 128;
    int n0 = blockIdx.x * 128;
    int chunk = n0 / nPerChunk;
    size_t boff = (size_t)chunk * chunkStride + (n0 % nPerChunk);
    const bf16* Bbh = Bhi + boff;
    const bf16* Bbl = Blo + boff;

    // staging coords: A 128 rows x 32 k, 2 thr/row; B 32 rows x 128 n, 8 thr/row
    int arow = tid >> 1, acol = (tid & 1) * 16;
    int brow = tid >> 3, bcol = (tid & 7) * 16;
    const bf16* Agh = Ahi + (size_t)(m0 + arow) * K + acol;
    const bf16* Agl = Alo + (size_t)(m0 + arow) * K + acol;

    int warp = tid >> 5, lane = tid & 31;
    int wm = (warp >> 2) * 64, wn = (warp & 3) * 32;
    int g = lane >> 2, ctg = lane & 3;
    int lrow = lane & 15, lcol8 = (lane >> 4) * 8;

    float acc[4][4][4];
    #pragma unroll
    for (int i = 0; i < 4; i++)
        #pragma unroll
        for (int j = 0; j < 4; j++)
            #pragma unroll
            for (int r = 0; r < 4; r++) acc[i][j][r] = 0.0f;

    int nt = K / 32;

    auto issue = [&](int kt, int buf) {
        bf16* as = As + buf * AS_E;
        bf16* bs = Bs + buf * BS_E;
        // A hi/lo
        {
            unsigned d0 = sptr(as + arow * ASB + acol);
            unsigned d1 = sptr(as + arow * ASB + 32 + acol);
            const bf16* s0 = Agh + kt * 32;
            const bf16* s1 = Agl + kt * 32;
            asm volatile("cp.async.cg.shared.global [%0], [%1], 16;" :: "r"(d0), "l"(s0));
            asm volatile("cp.async.cg.shared.global [%0], [%1], 16;" :: "r"(d0 + 16), "l"(s0 + 8));
            asm volatile("cp.async.cg.shared.global [%0], [%1], 16;" :: "r"(d1), "l"(s1));
            asm volatile("cp.async.cg.shared.global [%0], [%1], 16;" :: "r"(d1 + 16), "l"(s1 + 8));
        }
        // B hi/lo
        {
            unsigned d0 = sptr(bs + brow * BSB + bcol);
            unsigned d1 = sptr(bs + brow * BSB + 128 + bcol);
            const bf16* s0 = Bbh + (size_t)(kt * 32 + brow) * ldb + bcol;
            const bf16* s1 = Bbl + (size_t)(kt * 32 + brow) * ldb + bcol;
            asm volatile("cp.async.cg.shared.global [%0], [%1], 16;" :: "r"(d0), "l"(s0));
            asm volatile("cp.async.cg.shared.global [%0], [%1], 16;" :: "r"(d0 + 16), "l"(s0 + 8));
            asm volatile("cp.async.cg.shared.global [%0], [%1], 16;" :: "r"(d1), "l"(s1));
            asm volatile("cp.async.cg.shared.global [%0], [%1], 16;" :: "r"(d1 + 16), "l"(s1 + 8));
        }
        asm volatile("cp.async.commit_group;");
    };

    issue(0, 0);
    issue(1, 1);

    for (int kt = 0; kt < nt; kt++) {
        if (kt + 1 < nt) asm volatile("cp.async.wait_group 1;");
        else             asm volatile("cp.async.wait_group 0;");
        __syncthreads();

        const bf16* as = As + (kt & 1) * AS_E;
        const bf16* bs = Bs + (kt & 1) * BS_E;

        #pragma unroll
        for (int ks = 0; ks < 32; ks += 16) {
            unsigned bh[4][2], bl[4][2];
            #pragma unroll
            for (int nj = 0; nj < 2; nj++) {
                unsigned addr = sptr(bs + (ks + lrow) * BSB + wn + 16 * nj + lcol8);
                unsigned t0, t1, t2, t3;
                asm volatile("ldmatrix.sync.aligned.m8n8.x4.trans.shared.b16 "
                             "{%0,%1,%2,%3}, [%4];"
                             : "=r"(t0), "=r"(t1), "=r"(t2), "=r"(t3) : "r"(addr));
                bh[2 * nj][0] = t0; bh[2 * nj][1] = t1;
                bh[2 * nj + 1][0] = t2; bh[2 * nj + 1][1] = t3;
                asm volatile("ldmatrix.sync.aligned.m8n8.x4.trans.shared.b16 "
                             "{%0,%1,%2,%3}, [%4];"
                             : "=r"(t0), "=r"(t1), "=r"(t2), "=r"(t3)
                             : "r"(addr + 256));
                bl[2 * nj][0] = t0; bl[2 * nj][1] = t1;
                bl[2 * nj + 1][0] = t2; bl[2 * nj + 1][1] = t3;
            }
            #pragma unroll
            for (int i = 0; i < 4; i++) {
                unsigned ah[4], al[4];
                unsigned addr = sptr(as + (wm + 16 * i + lrow) * ASB + ks + lcol8);
                asm volatile("ldmatrix.sync.aligned.m8n8.x4.shared.b16 "
                             "{%0,%1,%2,%3}, [%4];"
                             : "=r"(ah[0]), "=r"(ah[1]), "=r"(ah[2]), "=r"(ah[3])
                             : "r"(addr));
                asm volatile("ldmatrix.sync.aligned.m8n8.x4.shared.b16 "
                             "{%0,%1,%2,%3}, [%4];"
                             : "=r"(al[0]), "=r"(al[1]), "=r"(al[2]), "=r"(al[3])
                             : "r"(addr + 64));
                #pragma unroll
                for (int j = 0; j < 4; j++) {
                    MMA_BF16(acc[i][j], ah, bh[j]);
                    MMA_BF16(acc[i][j], ah, bl[j]);
                    MMA_BF16(acc[i][j], al, bh[j]);
                }
            }
        }
        __syncthreads();
        if (kt + 2 < nt) issue(kt + 2, kt & 1);
    }

    // ---- epilogue ----
    #pragma unroll
    for (int i = 0; i < 4; i++) {
        int mrow = m0 + wm + 16 * i + g;
        #pragma unroll
        for (int j = 0; j < 4; j++) {
            int n = n0 + wn + 8 * j + 2 * ctg;
            float2 bv = *(const float2*)(bias + n);
            float v0 = acc[i][j][0] + bv.x, v1 = acc[i][j][1] + bv.y;
            float v2 = acc[i][j][2] + bv.x, v3 = acc[i][j][3] + bv.y;
            if (RES) {
                float2 r0 = *(const float2*)(Res + (size_t)mrow * ldc + n);
                float2 r1 = *(const float2*)(Res + (size_t)(mrow + 8) * ldc + n);
                v0 += r0.x; v1 += r0.y; v2 += r1.x; v3 += r1.y;
            }
            if (RELU) {
                v0 = fmaxf(v0, 0.0f); v1 = fmaxf(v1, 0.0f);
                v2 = fmaxf(v2, 0.0f); v3 = fmaxf(v3, 0.0f);
            }
            if (WF32) {
                *(float2*)(C + (size_t)mrow * ldc + n) = make_float2(v0, v1);
                *(float2*)(C + (size_t)(mrow + 8) * ldc + n) = make_float2(v2, v3);
            }
            if (WBF) {
                unsigned hp, lp;
                split2(v0, v1, hp, lp);
                *(unsigned*)(Chi + (size_t)mrow * ldc + n) = hp;
                *(unsigned*)(Clo + (size_t)mrow * ldc + n) = lp;
                split2(v2, v3, hp, lp);
                *(unsigned*)(Chi + (size_t)(mrow + 8) * ldc + n) = hp;
                *(unsigned*)(Clo + (size_t)(mrow + 8) * ldc + n) = lp;
            }
        }
    }
}

// ---------------- fp32 fallback GEMM (out-projection, N=400) ----------------
__global__ void __launch_bounds__(256) sgemm_kernel(
    const float* __restrict__ A, const float* __restrict__ B,
    const float* __restrict__ bias, float* __restrict__ C,
    int M, int N, int K, int ldb, int ldc)
{
    __shared__ float As[16][128];
    __shared__ float Bs[16][128];

    int tid = threadIdx.x;
    int m0 = blockIdx.y * 128;
    int n0 = blockIdx.x * 128;
    bool fullN = (n0 + 128 <= N);

    float acc[8][8];
    #pragma unroll
    for (int i = 0; i < 8; i++)
        #pragma unroll
        for (int j = 0; j < 8; j++) acc[i][j] = 0.0f;

    int a_r = tid >> 2, a_c = (tid & 3) << 2;
    int b_r = tid >> 5, b_c = (tid & 31) << 2;
    int mm = (tid >> 4) << 3;
    int nn = (tid & 15) << 3;

    for (int kt = 0; kt < K; kt += 16) {
        #pragma unroll
        for (int p = 0; p < 2; p++) {
            int r = a_r + p * 64;
            float4 f = *(const float4*)(A + (size_t)(m0 + r) * K + kt + a_c);
            As[a_c + 0][r] = f.x; As[a_c + 1][r] = f.y;
            As[a_c + 2][r] = f.z; As[a_c + 3][r] = f.w;
        }
        #pragma unroll
        for (int p = 0; p < 2; p++) {
            int r = b_r + p * 8;
            const float* src = B + (size_t)(kt + r) * ldb + n0 + b_c;
            float4 f;
            if (fullN) {
                f = *(const float4*)src;
            } else {
                f.x = (n0 + b_c + 0 < N) ? src[0] : 0.0f;
                f.y = (n0 + b_c + 1 < N) ? src[1] : 0.0f;
                f.z = (n0 + b_c + 2 < N) ? src[2] : 0.0f;
                f.w = (n0 + b_c + 3 < N) ? src[3] : 0.0f;
            }
            *(float4*)(&Bs[r][b_c]) = f;
        }
        __syncthreads();

        #pragma unroll
        for (int k = 0; k < 16; k++) {
            float a[8], bb[8];
            *(float4*)(a)      = *(const float4*)(&As[k][mm]);
            *(float4*)(a + 4)  = *(const float4*)(&As[k][mm + 4]);
            *(float4*)(bb)     = *(const float4*)(&Bs[k][nn]);
            *(float4*)(bb + 4) = *(const float4*)(&Bs[k][nn + 4]);
            #pragma unroll
            for (int i = 0; i < 8; i++)
                #pragma unroll
                for (int j = 0; j < 8; j++)
                    acc[i][j] = fmaf(a[i], bb[j], acc[i][j]);
        }
        __syncthreads();
    }

    #pragma unroll
    for (int i = 0; i < 8; i++) {
        int m = m0 + mm + i;
        #pragma unroll
        for (int j = 0; j < 8; j++) {
            int n = n0 + nn + j;
            if (n < N) C[(size_t)m * ldc + n] = acc[i][j] + bias[n];
        }
    }
}

// ---------------- launch ----------------
extern "C" void kernel_launch(void* const* d_in, const int* in_sizes, int n_in,
                              void* d_out, int out_size)
{
    const int*   x    = (const int*)d_in[0];
    const float* emb  = (const float*)d_in[1];
    const float* Wqkv = (const float*)d_in[2];
    const float* bqkv = (const float*)d_in[3];
    const float* Wo   = (const float*)d_in[4];
    const float* bo   = (const float*)d_in[5];
    const float* ln1g = (const float*)d_in[6];
    const float* ln1b = (const float*)d_in[7];
    const float* W1   = (const float*)d_in[8];
    const float* b1   = (const float*)d_in[9];
    const float* W2   = (const float*)d_in[10];
    const float* b2   = (const float*)d_in[11];
    const float* ln2g = (const float*)d_in[12];
    const float* ln2b = (const float*)d_in[13];
    const float* lnfg = (const float*)d_in[14];
    const float* lnfb = (const float*)d_in[15];
    const float* Wout = (const float*)d_in[16];
    const float* bout = (const float*)d_in[17];
    float* out = (float*)d_out;

    float *h, *qkv, *state, *zbuf;
    bf16 *hhi, *hlo, *ahi, *alo, *fhi, *flo, *whi, *wlo;
    cudaGetSymbolAddress((void**)&h,    g_h);
    cudaGetSymbolAddress((void**)&qkv,  g_qkv);
    cudaGetSymbolAddress((void**)&state, g_state);
    cudaGetSymbolAddress((void**)&zbuf, g_z);
    cudaGetSymbolAddress((void**)&hhi,  g_h_hi);
    cudaGetSymbolAddress((void**)&hlo,  g_h_lo);
    cudaGetSymbolAddress((void**)&ahi,  g_attn_hi);
    cudaGetSymbolAddress((void**)&alo,  g_attn_lo);
    cudaGetSymbolAddress((void**)&fhi,  g_ff_hi);
    cudaGetSymbolAddress((void**)&flo,  g_ff_lo);
    cudaGetSymbolAddress((void**)&whi,  g_w_hi);
    cudaGetSymbolAddress((void**)&wlo,  g_w_lo);

    cudaFuncSetAttribute(tgemm_kernel<false, false, true, false>,
                         cudaFuncAttributeMaxDynamicSharedMemorySize, TG_SMEM);
    cudaFuncSetAttribute(tgemm_kernel<false, true, true, false>,
                         cudaFuncAttributeMaxDynamicSharedMemorySize, TG_SMEM);
    cudaFuncSetAttribute(tgemm_kernel<true, false, false, true>,
                         cudaFuncAttributeMaxDynamicSharedMemorySize, TG_SMEM);

    // split all weights into bf16 hi/lo (per replay; ~80us)
    split_kernel<<<(OFF_WO) / 4 / 256, 256>>>(Wqkv, whi + OFF_QKV, wlo + OFF_QKV, OFF_WO / 4);
    split_kernel<<<(OFF_W1 - OFF_WO) / 4 / 256, 256>>>(Wo, whi + OFF_WO, wlo + OFF_WO, (OFF_W1 - OFF_WO) / 4);
    split_kernel<<<(OFF_W2 - OFF_W1) / 4 / 256, 256>>>(W1, whi + OFF_W1, wlo + OFF_W1, (OFF_W2 - OFF_W1) / 4);
    split_kernel<<<(W_TOTAL - OFF_W2) / 4 / 256, 256>>>(W2, whi + OFF_W2, wlo + OFF_W2, (W_TOTAL - OFF_W2) / 4);

    embed_kernel<<<TOKENS, 128>>>(x, emb, h, hhi, hlo);

    dim3 gQKV(12, TOKENS / 128);
    dim3 gN512(4, TOKENS / 128);
    dim3 gN2048(16, TOKENS / 128);
    dim3 gAttn(32, NP);
    dim3 gNout((NVOCAB + 127) / 128, TOKENS / 128);

    for (int l = 0; l < NLAYER; l++) {
        // qkv = h @ [Wq|Wk|Wv] + b  (fp32 out)
        tgemm_kernel<false, false, true, false><<<gQKV, 256, TG_SMEM>>>(
            hhi, hlo,
            whi + OFF_QKV + (size_t)l * 3 * DM * DM, wlo + OFF_QKV + (size_t)l * 3 * DM * DM,
            bqkv + (size_t)l * 3 * DM, nullptr,
            qkv, nullptr, nullptr,
            TOKENS, 3 * DM, DM, DM, DM, (size_t)DM * DM, 3 * DM);

        attn_sums_kernel<<<gAttn, 64>>>(qkv, state, zbuf);
        attn_prefix_kernel<<<32, 256>>>(state, zbuf);
        attn_scan_kernel<<<gAttn, 64>>>(qkv, state, zbuf, ahi, alo);

        // h = h + attn @ Wo + bo  (fp32 out)
        tgemm_kernel<false, true, true, false><<<gN512, 256, TG_SMEM>>>(
            ahi, alo,
            whi + OFF_WO + (size_t)l * DM * DM, wlo + OFF_WO + (size_t)l * DM * DM,
            bo + (size_t)l * DM, h,
            h, nullptr, nullptr,
            TOKENS, DM, DM, DM, DM, 0, DM);
        ln_kernel<<<TOKENS, 128>>>(h, ln1g + l * DM, ln1b + l * DM, h, hhi, hlo);

        // ff = relu(h @ W1 + b1)  (bf16 hi/lo out only)
        tgemm_kernel<true, false, false, true><<<gN2048, 256, TG_SMEM>>>(
            hhi, hlo,
            whi + OFF_W1 + (size_t)l * DM * DFF, wlo + OFF_W1 + (size_t)l * DM * DFF,
            b1 + (size_t)l * DFF, nullptr,
            nullptr, fhi, flo,
            TOKENS, DFF, DM, DFF, DFF, 0, DFF);

        // h = h + ff @ W2 + b2  (fp32 out)
        tgemm_kernel<false, true, true, false><<<gN512, 256, TG_SMEM>>>(
            fhi, flo,
            whi + OFF_W2 + (size_t)l * DFF * DM, wlo + OFF_W2 + (size_t)l * DFF * DM,
            b2 + (size_t)l * DM, h,
            h, nullptr, nullptr,
            TOKENS, DM, DFF, DM, DM, 0, DM);
        ln_kernel<<<TOKENS, 128>>>(h, ln2g + l * DM, ln2b + l * DM, h, hhi, hlo);
    }

    ln_kernel<<<TOKENS, 128>>>(h, lnfg, lnfb, h, nullptr, nullptr);
    sgemm_kernel<<<gNout, 256>>>(h, Wout, bout, out, TOKENS, NVOCAB, DM, NVOCAB, NVOCAB);
}